// round 11
// baseline (speedup 1.0000x reference)
#include <cuda_runtime.h>
#include <cuda_bf16.h>
#include <math.h>
#include <stdint.h>

// Problem constants (fixed by the dataset)
#define D        512
#define MAX_B    128
#define MAX_M    6304
#define MAXK     64
#define NCAND    96     // bf16-stage candidates (true top-50 inside, ~50 sigma margin)
#define GN       32     // mem rows per MMA CTA; 6304 = 32*197 exactly
#define SAPAD    72     // smem row pitch (bf16 elems): lane stride 144B -> bank-conflict-free

// ---------------- scratch (no allocations allowed) ----------------
__device__ float g_cos[MAX_B * MAX_M];    // approx (bf16) cosine sims [B, M]
__device__ float g_qinv[MAX_B];           // 1/max(||q||, eps)
__device__ float g_minv[MAX_M];           // 1/max(||mem||, eps)
__device__ int   g_cand[MAX_B * NCAND];   // candidate indices (bf16 stage)
__device__ int   g_idx[MAX_B * MAXK];     // final top-k block indices
__device__ float g_wgt[MAX_B * MAXK];     // softmax weights * scalar weight

__device__ __forceinline__ uint32_t smem_u32(const void* p) {
    uint32_t a;
    asm("{ .reg .u64 t; cvta.to.shared.u64 t, %1; cvt.u32.u64 %0, t; }"
        : "=r"(a) : "l"(p));
    return a;
}

__device__ __forceinline__ uint4 pack8(float4 f0, float4 f1) {
    union { __nv_bfloat16 h[8]; uint4 v; } p;
    p.h[0] = __float2bfloat16(f0.x); p.h[1] = __float2bfloat16(f0.y);
    p.h[2] = __float2bfloat16(f0.z); p.h[3] = __float2bfloat16(f0.w);
    p.h[4] = __float2bfloat16(f1.x); p.h[5] = __float2bfloat16(f1.y);
    p.h[6] = __float2bfloat16(f1.z); p.h[7] = __float2bfloat16(f1.w);
    return p.v;
}

// ---------------- Kernel 1: inverse norms ----------------
__global__ void norm_kernel(const float* __restrict__ q,
                            const float* __restrict__ mem, int B) {
    int r = blockIdx.x;
    const float* src = (r < B) ? (q + (long)r * D) : (mem + (long)(r - B) * D);
    float4 v = ((const float4*)src)[threadIdx.x];
    float ss = v.x * v.x + v.y * v.y + v.z * v.z + v.w * v.w;
    #pragma unroll
    for (int o = 16; o; o >>= 1) ss += __shfl_xor_sync(0xffffffffu, ss, o);
    __shared__ float sred[4];
    if ((threadIdx.x & 31) == 0) sred[threadIdx.x >> 5] = ss;
    __syncthreads();
    if (threadIdx.x == 0) {
        float t = sred[0] + sred[1] + sred[2] + sred[3];
        float inv = 1.0f / fmaxf(sqrtf(t), 1e-8f);
        if (r < B) g_qinv[r] = inv;
        else       g_minv[r - B] = inv;
    }
}

// ---------------- Kernel 2: bf16 HMMA GEMM -> approx cos ----------------
// C[128 b, 32 n] per CTA over K=512 (8 chunks of 64, double-buffered).
// mma.sync.m16n8k16 bf16, ldmatrix-fed, fp32->bf16 conversion on the fly.
__global__ void __launch_bounds__(256, 1)
mma_cos_kernel(const float* __restrict__ q,
               const float* __restrict__ mem, int M) {
    __shared__ __align__(16) __nv_bfloat16 sA[2][128][SAPAD];  // 36 KB
    __shared__ __align__(16) __nv_bfloat16 sB[2][GN][SAPAD];   //  9 KB

    int tid = threadIdx.x, lane = tid & 31, w = tid >> 5;
    int n0 = blockIdx.x * GN;

    // global->reg load assignments (fixed per thread)
    int arow = tid >> 1, acol = (tid & 1) * 32;  // A: 128 rows x 64 cols
    int brow = tid >> 3, bcol = (tid & 7) * 8;   // B:  32 rows x 64 cols

    uint4 ra[4], rb;

    #define LOADG(c)                                                           \
        do {                                                                   \
            const float4* As = (const float4*)(q + (long)arow * D + (c) * 64 + acol); \
            _Pragma("unroll")                                                  \
            for (int u = 0; u < 4; u++) ra[u] = pack8(As[2 * u], As[2 * u + 1]); \
            int grow = n0 + brow;                                              \
            if (grow < M) {                                                    \
                const float4* Bs = (const float4*)(mem + (long)grow * D + (c) * 64 + bcol); \
                rb = pack8(Bs[0], Bs[1]);                                      \
            } else rb = make_uint4(0, 0, 0, 0);                                \
        } while (0)

    #define STORES(buf)                                                        \
        do {                                                                   \
            _Pragma("unroll")                                                  \
            for (int u = 0; u < 4; u++)                                        \
                *(uint4*)&sA[buf][arow][acol + 8 * u] = ra[u];                 \
            *(uint4*)&sB[buf][brow][bcol] = rb;                                \
        } while (0)

    float acc[4][4];
    #pragma unroll
    for (int t = 0; t < 4; t++)
        #pragma unroll
        for (int i = 0; i < 4; i++) acc[t][i] = 0.0f;

    uint32_t sAb = smem_u32(&sA[0][0][0]);
    uint32_t sBb = smem_u32(&sB[0][0][0]);
    const uint32_t szA = 128 * SAPAD * 2, szB = GN * SAPAD * 2;

    // ldmatrix per-lane addressing (bytes)
    int row16 = lane & 15, kh = lane >> 4;               // A
    int bmat = lane >> 3, br8 = lane & 7;                // B
    int bkoff = (bmat & 1) * 8;
    int bnbase = (bmat >> 1) * 8 + br8;

    LOADG(0);
    STORES(0);
    __syncthreads();

    #pragma unroll 1
    for (int c = 0; c < 8; c++) {
        int buf = c & 1;
        if (c < 7) LOADG(c + 1);                 // overlap LDG with HMMA
        uint32_t abase = sAb + buf * szA + (w * 16 + row16) * (SAPAD * 2);
        uint32_t bbase = sBb + buf * szB;
        #pragma unroll
        for (int ks = 0; ks < 4; ks++) {
            uint32_t a0, a1, a2, a3;
            uint32_t aaddr = abase + (ks * 16 + kh * 8) * 2;
            asm volatile(
                "ldmatrix.sync.aligned.m8n8.x4.shared.b16 {%0,%1,%2,%3}, [%4];"
                : "=r"(a0), "=r"(a1), "=r"(a2), "=r"(a3) : "r"(aaddr));
            #pragma unroll
            for (int half = 0; half < 2; half++) {
                int nrow = half * 16 + bnbase;
                uint32_t baddr = bbase + nrow * (SAPAD * 2) + (ks * 16 + bkoff) * 2;
                uint32_t b0, b1, b2, b3;
                asm volatile(
                    "ldmatrix.sync.aligned.m8n8.x4.shared.b16 {%0,%1,%2,%3}, [%4];"
                    : "=r"(b0), "=r"(b1), "=r"(b2), "=r"(b3) : "r"(baddr));
                int t0 = half * 2;
                asm volatile(
                    "mma.sync.aligned.m16n8k16.row.col.f32.bf16.bf16.f32 "
                    "{%0,%1,%2,%3}, {%4,%5,%6,%7}, {%8,%9}, {%0,%1,%2,%3};"
                    : "+f"(acc[t0][0]), "+f"(acc[t0][1]),
                      "+f"(acc[t0][2]), "+f"(acc[t0][3])
                    : "r"(a0), "r"(a1), "r"(a2), "r"(a3), "r"(b0), "r"(b1));
                asm volatile(
                    "mma.sync.aligned.m16n8k16.row.col.f32.bf16.bf16.f32 "
                    "{%0,%1,%2,%3}, {%4,%5,%6,%7}, {%8,%9}, {%0,%1,%2,%3};"
                    : "+f"(acc[t0 + 1][0]), "+f"(acc[t0 + 1][1]),
                      "+f"(acc[t0 + 1][2]), "+f"(acc[t0 + 1][3])
                    : "r"(a0), "r"(a1), "r"(a2), "r"(a3), "r"(b2), "r"(b3));
            }
        }
        if (c < 7) {
            STORES(buf ^ 1);
            __syncthreads();
        }
    }

    // Epilogue: c0,c1 -> row l/4, cols 2(l%4)+{0,1}; c2,c3 -> row l/4+8.
    int r0 = w * 16 + (lane >> 2);
    float qi0 = g_qinv[r0], qi1 = g_qinv[r0 + 8];
    #pragma unroll
    for (int t = 0; t < 4; t++) {
        int col = n0 + t * 8 + 2 * (lane & 3);
        if (col < M) {
            float m0 = g_minv[col], m1 = g_minv[col + 1];
            float2 lo = make_float2(acc[t][0] * qi0 * m0, acc[t][1] * qi0 * m1);
            float2 hi = make_float2(acc[t][2] * qi1 * m0, acc[t][3] * qi1 * m1);
            *(float2*)&g_cos[(long)r0 * M + col] = lo;
            *(float2*)&g_cos[(long)(r0 + 8) * M + col] = hi;
        }
    }
    #undef LOADG
    #undef STORES
}

// ---------------- Kernel 3: candidate select (top-NCAND) via radix ----------
#define TKT 512
__device__ __forceinline__ unsigned map_f(float f) {
    unsigned u = __float_as_uint(f);
    return (u & 0x80000000u) ? ~u : (u | 0x80000000u);
}

__global__ void cand_kernel(int M) {
    __shared__ unsigned mv[MAX_M];
    __shared__ int hist[256];
    __shared__ int warpsum[TKT / 32];
    __shared__ int warpoff[TKT / 32];
    __shared__ unsigned s_pref;
    __shared__ int s_kneed;
    __shared__ int s_totGT;
    __shared__ int topi[NCAND];

    int b = blockIdx.x;
    int tid = threadIdx.x;
    int lane = tid & 31, wrp = tid >> 5;
    const float* row = g_cos + (long)b * M;

    for (int i = tid; i < M; i += TKT) mv[i] = map_f(row[i]);

    const int kk = NCAND;
    if (tid == 0) { s_pref = 0u; s_kneed = kk; }
    __syncthreads();

    for (int shift = 24; shift >= 0; shift -= 8) {
        if (tid < 256) hist[tid] = 0;
        __syncthreads();
        unsigned dmask = (shift == 24) ? 0u : (0xFFFFFFFFu << (shift + 8));
        unsigned pref = s_pref;
        for (int i = tid; i < M; i += TKT) {
            unsigned v = mv[i];
            if ((v & dmask) == pref) atomicAdd(&hist[(v >> shift) & 255], 1);
        }
        __syncthreads();
        if (tid < 32) {
            int s = 0;
            #pragma unroll
            for (int j = 0; j < 8; j++) s += hist[tid * 8 + j];
            int suf = s;
            #pragma unroll
            for (int o = 1; o < 32; o <<= 1) {
                int u = __shfl_down_sync(0xffffffffu, suf, o);
                if (tid + o < 32) suf += u;
            }
            int sufNext = __shfl_down_sync(0xffffffffu, suf, 1);
            if (tid == 31) sufNext = 0;
            int kneed = s_kneed;
            if (kneed <= suf && kneed > sufNext) {
                int c = sufNext;
                #pragma unroll
                for (int d = 7; d >= 0; d--) {
                    int bin = tid * 8 + d;
                    c += hist[bin];
                    if (c >= kneed) {
                        s_kneed = kneed - (c - hist[bin]);
                        s_pref  = pref | ((unsigned)bin << shift);
                        break;
                    }
                }
            }
        }
        __syncthreads();
    }

    unsigned T = s_pref;

    int cntGT = 0, cntEQ = 0;
    for (int i = tid; i < M; i += TKT) {
        unsigned v = mv[i];
        cntGT += (v > T);
        cntEQ += (v == T);
    }
    int packed = cntGT | (cntEQ << 16);
    int v = packed;
    #pragma unroll
    for (int o = 1; o < 32; o <<= 1) {
        int u = __shfl_up_sync(0xffffffffu, v, o);
        if (lane >= o) v += u;
    }
    if (lane == 31) warpsum[wrp] = v;
    __syncthreads();
    if (tid == 0) {
        int acc = 0;
        #pragma unroll
        for (int w = 0; w < TKT / 32; w++) { warpoff[w] = acc; acc += warpsum[w]; }
        s_totGT = acc & 0xffff;
    }
    __syncthreads();
    int ex = v - packed + warpoff[wrp];
    int gtPos = ex & 0xffff;
    int eqPos = s_totGT + (ex >> 16);
    for (int i = tid; i < M; i += TKT) {
        unsigned val = mv[i];
        if (val > T) {
            topi[gtPos++] = i;
        } else if (val == T) {
            if (eqPos < kk) topi[eqPos] = i;
            eqPos++;
        }
    }
    __syncthreads();
    if (tid < NCAND) g_cand[b * NCAND + tid] = topi[tid];
}

// ---------------- Kernel 4: exact fp32 rescore + top-k + softmax ------------
__global__ void rescore_kernel(const float* __restrict__ q,
                               const float* __restrict__ mem,
                               const float* __restrict__ wscalar,
                               const int* __restrict__ kp, int M) {
    __shared__ float sq[D];
    __shared__ int   scidx[NCAND];
    __shared__ float scv[NCAND];
    __shared__ int   srank[NCAND];
    __shared__ float s_mx, s_sum;

    int b = blockIdx.x, tid = threadIdx.x, lane = tid & 31, w = tid >> 5;
    if (tid < 128) ((float4*)sq)[tid] = ((const float4*)(q + (long)b * D))[tid];
    if (tid < NCAND) scidx[tid] = g_cand[b * NCAND + tid];
    __syncthreads();

    float qi = g_qinv[b];
    const float4* q4 = (const float4*)sq;
    #pragma unroll 1
    for (int t = 0; t < NCAND / 8; t++) {          // 12 per warp
        int ci = w * (NCAND / 8) + t;
        int idx = scidx[ci];
        const float4* mr = (const float4*)(mem + (long)idx * D);
        float acc = 0.f;
        #pragma unroll
        for (int j = 0; j < 4; j++) {
            float4 mv = mr[lane + j * 32];
            float4 qv = q4[lane + j * 32];
            acc += mv.x * qv.x + mv.y * qv.y + mv.z * qv.z + mv.w * qv.w;
        }
        #pragma unroll
        for (int o = 16; o; o >>= 1) acc += __shfl_xor_sync(0xffffffffu, acc, o);
        if (lane == 0) scv[ci] = acc * qi * g_minv[idx];
    }
    __syncthreads();

    int k = kp ? *kp : 50;
    if (k > MAXK) k = MAXK;
    if (k < 1) k = 1;

    if (tid < NCAND) {
        float vi = scv[tid]; int ii = scidx[tid]; int r = 0;
        for (int j = 0; j < NCAND; j++) {
            float vj = scv[j];
            r += (vj > vi) || (vj == vi && scidx[j] < ii);   // jax tie: low idx first
        }
        srank[tid] = r;
    }
    __syncthreads();
    if (tid == 0) {
        float mx = -1e30f;
        for (int j = 0; j < NCAND; j++) if (srank[j] < k) mx = fmaxf(mx, scv[j]);
        float s = 0.f;
        for (int j = 0; j < NCAND; j++) if (srank[j] < k) s += expf(scv[j] - mx);
        s_mx = mx; s_sum = s;
    }
    __syncthreads();
    if (tid < NCAND && srank[tid] < k) {
        float wsc = wscalar[0];
        g_idx[b * MAXK + srank[tid]] = scidx[tid];
        g_wgt[b * MAXK + srank[tid]] = expf(scv[tid] - s_mx) / s_sum * wsc;
    }
}

// ---------------- Kernel 5: gather + weighted reduce + blend (unchanged) ----
__global__ void gather_kernel(const float4* __restrict__ fp,
                              const float4* __restrict__ enc,
                              const float* __restrict__ wscalar,
                              const int* __restrict__ kp,
                              float4* __restrict__ out, int nvec) {
    __shared__ int   sidx[MAXK];
    __shared__ float sw[MAXK];
    int b = blockIdx.x;
    int k = kp ? *kp : 50;
    if (k > MAXK) k = MAXK;
    if (k < 1) k = 1;
    if (threadIdx.x < k) {
        sidx[threadIdx.x] = g_idx[b * MAXK + threadIdx.x];
        sw[threadIdx.x]   = g_wgt[b * MAXK + threadIdx.x];
    }
    __syncthreads();

    int pos = blockIdx.y * blockDim.x + threadIdx.x;
    if (pos >= nvec) return;

    float ax = 0.f, ay = 0.f, az = 0.f, aw = 0.f;
    int j = 0;
    for (; j + 4 <= k; j += 4) {
        float4 v0 = fp[(long)sidx[j + 0] * nvec + pos];
        float4 v1 = fp[(long)sidx[j + 1] * nvec + pos];
        float4 v2 = fp[(long)sidx[j + 2] * nvec + pos];
        float4 v3 = fp[(long)sidx[j + 3] * nvec + pos];
        float w0 = sw[j + 0], w1 = sw[j + 1], w2 = sw[j + 2], w3 = sw[j + 3];
        ax = fmaf(w0, v0.x, ax); ay = fmaf(w0, v0.y, ay);
        az = fmaf(w0, v0.z, az); aw = fmaf(w0, v0.w, aw);
        ax = fmaf(w1, v1.x, ax); ay = fmaf(w1, v1.y, ay);
        az = fmaf(w1, v1.z, az); aw = fmaf(w1, v1.w, aw);
        ax = fmaf(w2, v2.x, ax); ay = fmaf(w2, v2.y, ay);
        az = fmaf(w2, v2.z, az); aw = fmaf(w2, v2.w, aw);
        ax = fmaf(w3, v3.x, ax); ay = fmaf(w3, v3.y, ay);
        az = fmaf(w3, v3.z, az); aw = fmaf(w3, v3.w, aw);
    }
    for (; j < k; j++) {
        float4 vv = fp[(long)sidx[j] * nvec + pos];
        float w = sw[j];
        ax = fmaf(w, vv.x, ax); ay = fmaf(w, vv.y, ay);
        az = fmaf(w, vv.z, az); aw = fmaf(w, vv.w, aw);
    }
    float om = 1.0f - wscalar[0];
    float4 e = enc[(long)b * nvec + pos];
    float4 r;
    r.x = fmaf(om, e.x, ax);
    r.y = fmaf(om, e.y, ay);
    r.z = fmaf(om, e.z, az);
    r.w = fmaf(om, e.w, aw);
    out[(long)b * nvec + pos] = r;
}

// ---------------- launch ----------------
extern "C" void kernel_launch(void* const* d_in, const int* in_sizes, int n_in,
                              void* d_out, int out_size) {
    const float* enc = (const float*)d_in[0];
    const float* q   = (const float*)d_in[1];
    const float* mem = (const float*)d_in[2];
    const float* fp  = (const float*)d_in[3];
    const float* wt  = (const float*)d_in[4];
    const int*   kp  = (n_in > 5) ? (const int*)d_in[5] : nullptr;

    int B = in_sizes[1] / D;                // 128
    int M = in_sizes[2] / D;                // 6304
    int blk = in_sizes[0] / (B * D);        // 64
    int nvec = blk * D / 4;                 // 8192 float4 per batch

    norm_kernel<<<B + M, 128>>>(q, mem, B);

    int nct = (M + GN - 1) / GN;            // 197
    mma_cos_kernel<<<nct, 256>>>(q, mem, M);

    cand_kernel<<<B, TKT>>>(M);

    rescore_kernel<<<B, 256>>>(q, mem, wt, kp, M);

    dim3 grgrid(B, (nvec + 255) / 256);     // batch fastest -> L2 reuse
    gather_kernel<<<grgrid, 256>>>((const float4*)fp, (const float4*)enc,
                                   wt, kp, (float4*)d_out, nvec);
}

// round 14
// speedup vs baseline: 1.0310x; 1.0310x over previous
#include <cuda_runtime.h>
#include <cuda_bf16.h>
#include <math.h>
#include <stdint.h>

// Problem constants (fixed by the dataset)
#define D        512
#define MAX_B    128
#define MAX_M    6304
#define MAXK     64
#define NCAND    96     // bf16-stage candidates (true top-50 inside, ~50 sigma margin)
#define GN       32     // mem rows per MMA CTA tile; 6304 = 32*197 exactly
#define GB       64     // batch rows per MMA CTA tile (128 = 2*64)
#define SAPAD    72     // smem row pitch (bf16 elems)

// ---------------- scratch (no allocations allowed) ----------------
__device__ float g_cos[MAX_B * MAX_M];    // approx (bf16) cosine sims [B, M]
__device__ float g_qinv[MAX_B];           // 1/max(||q||, eps)
__device__ float g_minv[MAX_M];           // 1/max(||mem||, eps)
__device__ int   g_cand[MAX_B * NCAND];   // candidate indices (bf16 stage)
__device__ float g_rv[MAX_B * NCAND];     // exact fp32 rescored cos
__device__ int   g_idx[MAX_B * MAXK];     // final top-k block indices
__device__ float g_wgt[MAX_B * MAXK];     // softmax weights * scalar weight

__device__ __forceinline__ uint32_t smem_u32(const void* p) {
    uint32_t a;
    asm("{ .reg .u64 t; cvta.to.shared.u64 t, %1; cvt.u32.u64 %0, t; }"
        : "=r"(a) : "l"(p));
    return a;
}

__device__ __forceinline__ uint4 pack8(float4 f0, float4 f1) {
    union { __nv_bfloat16 h[8]; uint4 v; } p;
    p.h[0] = __float2bfloat16(f0.x); p.h[1] = __float2bfloat16(f0.y);
    p.h[2] = __float2bfloat16(f0.z); p.h[3] = __float2bfloat16(f0.w);
    p.h[4] = __float2bfloat16(f1.x); p.h[5] = __float2bfloat16(f1.y);
    p.h[6] = __float2bfloat16(f1.z); p.h[7] = __float2bfloat16(f1.w);
    return p.v;
}

// ---------------- Kernel 1: inverse norms ----------------
__global__ void norm_kernel(const float* __restrict__ q,
                            const float* __restrict__ mem, int B) {
    int r = blockIdx.x;
    const float* src = (r < B) ? (q + (long)r * D) : (mem + (long)(r - B) * D);
    float4 v = ((const float4*)src)[threadIdx.x];
    float ss = v.x * v.x + v.y * v.y + v.z * v.z + v.w * v.w;
    #pragma unroll
    for (int o = 16; o; o >>= 1) ss += __shfl_xor_sync(0xffffffffu, ss, o);
    __shared__ float sred[4];
    if ((threadIdx.x & 31) == 0) sred[threadIdx.x >> 5] = ss;
    __syncthreads();
    if (threadIdx.x == 0) {
        float t = sred[0] + sred[1] + sred[2] + sred[3];
        float inv = 1.0f / fmaxf(sqrtf(t), 1e-8f);
        if (r < B) g_qinv[r] = inv;
        else       g_minv[r - B] = inv;
    }
}

// ---------------- Kernel 2: bf16 HMMA GEMM -> approx cos ----------------
// CTA tile: 64 b x 32 n, 4 warps, grid (197, 2) = 394 CTAs (wave-smoothed).
// K=512 in 8 double-buffered chunks of 64; fp32->bf16 convert on the fly.
__global__ void __launch_bounds__(128, 1)
mma_cos_kernel(const float* __restrict__ q,
               const float* __restrict__ mem, int M) {
    __shared__ __align__(16) __nv_bfloat16 sA[2][GB][SAPAD];  // 18 KB
    __shared__ __align__(16) __nv_bfloat16 sB[2][GN][SAPAD];  //  9 KB

    int tid = threadIdx.x, lane = tid & 31, w = tid >> 5;   // 4 warps
    int n0 = blockIdx.x * GN;
    int b0 = blockIdx.y * GB;

    // global->reg load assignments (128 threads)
    int arow = tid >> 1, acol = (tid & 1) * 32;  // A: 64 rows x 64 cols, 4 uint4/thr
    int brow = tid >> 2, bcol = (tid & 3) * 16;  // B: 32 rows x 64 cols, 2 uint4/thr

    uint4 ra[4], rb[2];

    #define LOADG(c)                                                           \
        do {                                                                   \
            const float4* As = (const float4*)(q + (long)(b0 + arow) * D + (c) * 64 + acol); \
            _Pragma("unroll")                                                  \
            for (int u = 0; u < 4; u++) ra[u] = pack8(As[2 * u], As[2 * u + 1]); \
            const float4* Bs = (const float4*)(mem + (long)(n0 + brow) * D + (c) * 64 + bcol); \
            rb[0] = pack8(Bs[0], Bs[1]);                                       \
            rb[1] = pack8(Bs[2], Bs[3]);                                       \
        } while (0)

    #define STORES(buf)                                                        \
        do {                                                                   \
            _Pragma("unroll")                                                  \
            for (int u = 0; u < 4; u++)                                        \
                *(uint4*)&sA[buf][arow][acol + 8 * u] = ra[u];                 \
            *(uint4*)&sB[buf][brow][bcol] = rb[0];                             \
            *(uint4*)&sB[buf][brow][bcol + 8] = rb[1];                         \
        } while (0)

    float acc[4][4];
    #pragma unroll
    for (int t = 0; t < 4; t++)
        #pragma unroll
        for (int i = 0; i < 4; i++) acc[t][i] = 0.0f;

    uint32_t sAb = smem_u32(&sA[0][0][0]);
    uint32_t sBb = smem_u32(&sB[0][0][0]);
    const uint32_t szA = GB * SAPAD * 2, szB = GN * SAPAD * 2;

    // ldmatrix per-lane addressing
    int row16 = lane & 15, kh = lane >> 4;               // A
    int bmat = lane >> 3, br8 = lane & 7;                // B
    int bkoff = (bmat & 1) * 8;
    int bnbase = (bmat >> 1) * 8 + br8;

    LOADG(0);
    STORES(0);
    __syncthreads();

    #pragma unroll 1
    for (int c = 0; c < 8; c++) {
        int buf = c & 1;
        if (c < 7) LOADG(c + 1);                 // overlap LDG with HMMA
        uint32_t abase = sAb + buf * szA + (w * 16 + row16) * (SAPAD * 2);
        uint32_t bbase = sBb + buf * szB;
        #pragma unroll
        for (int ks = 0; ks < 4; ks++) {
            uint32_t a0, a1, a2, a3;
            uint32_t aaddr = abase + (ks * 16 + kh * 8) * 2;
            asm volatile(
                "ldmatrix.sync.aligned.m8n8.x4.shared.b16 {%0,%1,%2,%3}, [%4];"
                : "=r"(a0), "=r"(a1), "=r"(a2), "=r"(a3) : "r"(aaddr));
            #pragma unroll
            for (int half = 0; half < 2; half++) {
                int nrow = half * 16 + bnbase;
                uint32_t baddr = bbase + nrow * (SAPAD * 2) + (ks * 16 + bkoff) * 2;
                uint32_t b0r, b1r, b2r, b3r;
                asm volatile(
                    "ldmatrix.sync.aligned.m8n8.x4.shared.b16 {%0,%1,%2,%3}, [%4];"
                    : "=r"(b0r), "=r"(b1r), "=r"(b2r), "=r"(b3r) : "r"(baddr));
                int t0 = half * 2;
                asm volatile(
                    "mma.sync.aligned.m16n8k16.row.col.f32.bf16.bf16.f32 "
                    "{%0,%1,%2,%3}, {%4,%5,%6,%7}, {%8,%9}, {%0,%1,%2,%3};"
                    : "+f"(acc[t0][0]), "+f"(acc[t0][1]),
                      "+f"(acc[t0][2]), "+f"(acc[t0][3])
                    : "r"(a0), "r"(a1), "r"(a2), "r"(a3), "r"(b0r), "r"(b1r));
                asm volatile(
                    "mma.sync.aligned.m16n8k16.row.col.f32.bf16.bf16.f32 "
                    "{%0,%1,%2,%3}, {%4,%5,%6,%7}, {%8,%9}, {%0,%1,%2,%3};"
                    : "+f"(acc[t0 + 1][0]), "+f"(acc[t0 + 1][1]),
                      "+f"(acc[t0 + 1][2]), "+f"(acc[t0 + 1][3])
                    : "r"(a0), "r"(a1), "r"(a2), "r"(a3), "r"(b2r), "r"(b3r));
            }
        }
        if (c < 7) {
            STORES(buf ^ 1);
            __syncthreads();
        }
    }

    // Epilogue: c0,c1 -> row l/4, cols 2(l%4)+{0,1}; c2,c3 -> row l/4+8.
    int r0 = b0 + w * 16 + (lane >> 2);
    float qi0 = g_qinv[r0], qi1 = g_qinv[r0 + 8];
    #pragma unroll
    for (int t = 0; t < 4; t++) {
        int col = n0 + t * 8 + 2 * (lane & 3);
        float m0 = g_minv[col], m1 = g_minv[col + 1];
        float2 lo = make_float2(acc[t][0] * qi0 * m0, acc[t][1] * qi0 * m1);
        float2 hi = make_float2(acc[t][2] * qi1 * m0, acc[t][3] * qi1 * m1);
        *(float2*)&g_cos[(long)r0 * M + col] = lo;
        *(float2*)&g_cos[(long)(r0 + 8) * M + col] = hi;
    }
    #undef LOADG
    #undef STORES
}

// ---------------- Kernel 3: candidate select (top-NCAND) via radix ----------
#define TKT 512
__device__ __forceinline__ unsigned map_f(float f) {
    unsigned u = __float_as_uint(f);
    return (u & 0x80000000u) ? ~u : (u | 0x80000000u);
}

__global__ void cand_kernel(int M) {
    __shared__ unsigned mv[MAX_M];
    __shared__ int hist[256];
    __shared__ int warpsum[TKT / 32];
    __shared__ int warpoff[TKT / 32];
    __shared__ unsigned s_pref;
    __shared__ int s_kneed;
    __shared__ int s_totGT;
    __shared__ int topi[NCAND];

    int b = blockIdx.x;
    int tid = threadIdx.x;
    int lane = tid & 31, wrp = tid >> 5;
    const float* row = g_cos + (long)b * M;

    for (int i = tid; i < M; i += TKT) mv[i] = map_f(row[i]);

    const int kk = NCAND;
    if (tid == 0) { s_pref = 0u; s_kneed = kk; }
    __syncthreads();

    for (int shift = 24; shift >= 0; shift -= 8) {
        if (tid < 256) hist[tid] = 0;
        __syncthreads();
        unsigned dmask = (shift == 24) ? 0u : (0xFFFFFFFFu << (shift + 8));
        unsigned pref = s_pref;
        for (int i = tid; i < M; i += TKT) {
            unsigned v = mv[i];
            if ((v & dmask) == pref) atomicAdd(&hist[(v >> shift) & 255], 1);
        }
        __syncthreads();
        if (tid < 32) {
            int s = 0;
            #pragma unroll
            for (int j = 0; j < 8; j++) s += hist[tid * 8 + j];
            int suf = s;
            #pragma unroll
            for (int o = 1; o < 32; o <<= 1) {
                int u = __shfl_down_sync(0xffffffffu, suf, o);
                if (tid + o < 32) suf += u;
            }
            int sufNext = __shfl_down_sync(0xffffffffu, suf, 1);
            if (tid == 31) sufNext = 0;
            int kneed = s_kneed;
            if (kneed <= suf && kneed > sufNext) {
                int c = sufNext;
                #pragma unroll
                for (int d = 7; d >= 0; d--) {
                    int bin = tid * 8 + d;
                    c += hist[bin];
                    if (c >= kneed) {
                        s_kneed = kneed - (c - hist[bin]);
                        s_pref  = pref | ((unsigned)bin << shift);
                        break;
                    }
                }
            }
        }
        __syncthreads();
    }

    unsigned T = s_pref;

    int cntGT = 0, cntEQ = 0;
    for (int i = tid; i < M; i += TKT) {
        unsigned v = mv[i];
        cntGT += (v > T);
        cntEQ += (v == T);
    }
    int packed = cntGT | (cntEQ << 16);
    int v = packed;
    #pragma unroll
    for (int o = 1; o < 32; o <<= 1) {
        int u = __shfl_up_sync(0xffffffffu, v, o);
        if (lane >= o) v += u;
    }
    if (lane == 31) warpsum[wrp] = v;
    __syncthreads();
    if (tid == 0) {
        int acc = 0;
        #pragma unroll
        for (int w = 0; w < TKT / 32; w++) { warpoff[w] = acc; acc += warpsum[w]; }
        s_totGT = acc & 0xffff;
    }
    __syncthreads();
    int ex = v - packed + warpoff[wrp];
    int gtPos = ex & 0xffff;
    int eqPos = s_totGT + (ex >> 16);
    for (int i = tid; i < M; i += TKT) {
        unsigned val = mv[i];
        if (val > T) {
            topi[gtPos++] = i;
        } else if (val == T) {
            if (eqPos < kk) topi[eqPos] = i;
            eqPos++;
        }
    }
    __syncthreads();
    if (tid < NCAND) g_cand[b * NCAND + tid] = topi[tid];
}

// ---------------- Kernel 4a: exact fp32 rescore (one warp per candidate) ----
// grid (B, NCAND/8), 256 threads = 8 warps -> 12288 independent warp-tasks.
__global__ void rescore_dot(const float* __restrict__ q,
                            const float* __restrict__ mem) {
    int b = blockIdx.x;
    int lane = threadIdx.x & 31, w = threadIdx.x >> 5;
    int ci = blockIdx.y * 8 + w;
    int idx = g_cand[b * NCAND + ci];
    const float4* qr = (const float4*)(q + (long)b * D);
    const float4* mr = (const float4*)(mem + (long)idx * D);
    float acc = 0.f;
    #pragma unroll
    for (int j = 0; j < 4; j++) {
        float4 a = qr[lane + 32 * j];
        float4 m = mr[lane + 32 * j];
        acc += a.x * m.x + a.y * m.y + a.z * m.z + a.w * m.w;
    }
    #pragma unroll
    for (int o = 16; o; o >>= 1) acc += __shfl_xor_sync(0xffffffffu, acc, o);
    if (lane == 0) g_rv[b * NCAND + ci] = acc * g_qinv[b] * g_minv[idx];
}

// ---------------- Kernel 4b: final top-k + softmax over NCAND -------------
__global__ void final_topk(const float* __restrict__ wscalar,
                           const int* __restrict__ kp) {
    __shared__ float scv[NCAND];
    __shared__ int   scidx[NCAND];
    __shared__ int   srank[NCAND];
    __shared__ float s_mx, s_sum;

    int b = blockIdx.x, tid = threadIdx.x;   // 128 threads
    if (tid < NCAND) {
        scv[tid]   = g_rv[b * NCAND + tid];
        scidx[tid] = g_cand[b * NCAND + tid];
    }
    __syncthreads();

    int k = kp ? *kp : 50;
    if (k > MAXK) k = MAXK;
    if (k < 1) k = 1;

    if (tid < NCAND) {
        float vi = scv[tid]; int ii = scidx[tid]; int r = 0;
        for (int j = 0; j < NCAND; j++) {
            float vj = scv[j];
            r += (vj > vi) || (vj == vi && scidx[j] < ii);   // jax tie: low idx first
        }
        srank[tid] = r;
    }
    __syncthreads();
    if (tid == 0) {
        float mx = -1e30f;
        for (int j = 0; j < NCAND; j++) if (srank[j] < k) mx = fmaxf(mx, scv[j]);
        float s = 0.f;
        for (int j = 0; j < NCAND; j++) if (srank[j] < k) s += expf(scv[j] - mx);
        s_mx = mx; s_sum = s;
    }
    __syncthreads();
    if (tid < NCAND && srank[tid] < k) {
        float wsc = wscalar[0];
        g_idx[b * MAXK + srank[tid]] = scidx[tid];
        g_wgt[b * MAXK + srank[tid]] = expf(scv[tid] - s_mx) / s_sum * wsc;
    }
}

// ---------------- Kernel 5: gather + weighted reduce + blend (unchanged) ----
__global__ void gather_kernel(const float4* __restrict__ fp,
                              const float4* __restrict__ enc,
                              const float* __restrict__ wscalar,
                              const int* __restrict__ kp,
                              float4* __restrict__ out, int nvec) {
    __shared__ int   sidx[MAXK];
    __shared__ float sw[MAXK];
    int b = blockIdx.x;
    int k = kp ? *kp : 50;
    if (k > MAXK) k = MAXK;
    if (k < 1) k = 1;
    if (threadIdx.x < k) {
        sidx[threadIdx.x] = g_idx[b * MAXK + threadIdx.x];
        sw[threadIdx.x]   = g_wgt[b * MAXK + threadIdx.x];
    }
    __syncthreads();

    int pos = blockIdx.y * blockDim.x + threadIdx.x;
    if (pos >= nvec) return;

    float ax = 0.f, ay = 0.f, az = 0.f, aw = 0.f;
    int j = 0;
    for (; j + 4 <= k; j += 4) {
        float4 v0 = fp[(long)sidx[j + 0] * nvec + pos];
        float4 v1 = fp[(long)sidx[j + 1] * nvec + pos];
        float4 v2 = fp[(long)sidx[j + 2] * nvec + pos];
        float4 v3 = fp[(long)sidx[j + 3] * nvec + pos];
        float w0 = sw[j + 0], w1 = sw[j + 1], w2 = sw[j + 2], w3 = sw[j + 3];
        ax = fmaf(w0, v0.x, ax); ay = fmaf(w0, v0.y, ay);
        az = fmaf(w0, v0.z, az); aw = fmaf(w0, v0.w, aw);
        ax = fmaf(w1, v1.x, ax); ay = fmaf(w1, v1.y, ay);
        az = fmaf(w1, v1.z, az); aw = fmaf(w1, v1.w, aw);
        ax = fmaf(w2, v2.x, ax); ay = fmaf(w2, v2.y, ay);
        az = fmaf(w2, v2.z, az); aw = fmaf(w2, v2.w, aw);
        ax = fmaf(w3, v3.x, ax); ay = fmaf(w3, v3.y, ay);
        az = fmaf(w3, v3.z, az); aw = fmaf(w3, v3.w, aw);
    }
    for (; j < k; j++) {
        float4 vv = fp[(long)sidx[j] * nvec + pos];
        float w = sw[j];
        ax = fmaf(w, vv.x, ax); ay = fmaf(w, vv.y, ay);
        az = fmaf(w, vv.z, az); aw = fmaf(w, vv.w, aw);
    }
    float om = 1.0f - wscalar[0];
    float4 e = enc[(long)b * nvec + pos];
    float4 r;
    r.x = fmaf(om, e.x, ax);
    r.y = fmaf(om, e.y, ay);
    r.z = fmaf(om, e.z, az);
    r.w = fmaf(om, e.w, aw);
    out[(long)b * nvec + pos] = r;
}

// ---------------- launch ----------------
extern "C" void kernel_launch(void* const* d_in, const int* in_sizes, int n_in,
                              void* d_out, int out_size) {
    const float* enc = (const float*)d_in[0];
    const float* q   = (const float*)d_in[1];
    const float* mem = (const float*)d_in[2];
    const float* fp  = (const float*)d_in[3];
    const float* wt  = (const float*)d_in[4];
    const int*   kp  = (n_in > 5) ? (const int*)d_in[5] : nullptr;

    int B = in_sizes[1] / D;                // 128
    int M = in_sizes[2] / D;                // 6304
    int blk = in_sizes[0] / (B * D);        // 64
    int nvec = blk * D / 4;                 // 8192 float4 per batch

    norm_kernel<<<B + M, 128>>>(q, mem, B);

    dim3 ggrid(M / GN, B / GB);             // (197, 2)
    mma_cos_kernel<<<ggrid, 128>>>(q, mem, M);

    cand_kernel<<<B, TKT>>>(M);

    dim3 rgrid(B, NCAND / 8);               // (128, 12), warp per candidate
    rescore_dot<<<rgrid, 256>>>(q, mem);

    final_topk<<<B, 128>>>(wt, kp);

    dim3 grgrid(B, (nvec + 255) / 256);     // batch fastest -> L2 reuse
    gather_kernel<<<grgrid, 256>>>((const float4*)fp, (const float4*)enc,
                                   wt, kp, (float4*)d_out, nvec);
}